// round 5
// baseline (speedup 1.0000x reference)
#include <cuda_runtime.h>
#include <cstddef>
#include <cstdint>

// ----- problem dims -----
constexpr int NB = 16;
constexpr int NC = 512;
constexpr int NHEADS = 8;
constexpr int HD = 64;
constexpr int FF = 2048;
constexpr int LAYERS = 6;
constexpr int T = 1280;
constexpr int MROWS = NB * T; // 20480

// ----- scratch -----
__device__ float g_x [(size_t)MROWS * NC];
__device__ float g_h [(size_t)MROWS * NC];
__device__ float g_q [(size_t)MROWS * NC];
__device__ float g_k [(size_t)MROWS * NC];
__device__ float g_v [(size_t)MROWS * NC];
__device__ float g_y [(size_t)MROWS * NC];
__device__ float g_ff[(size_t)MROWS * FF];
__device__ float g_s [(size_t)NB * NHEADS * T * T];

// packed fp32x2 FMA (Blackwell FFMA2) --------------------------------
__device__ __forceinline__ void fma2(unsigned long long& d,
                                     unsigned long long a,
                                     unsigned long long b) {
    asm("fma.rn.f32x2 %0, %1, %2, %0;" : "+l"(d) : "l"(a), "l"(b));
}
__device__ __forceinline__ float2 unpk(unsigned long long v) {
    float2 r;
    r.x = __uint_as_float((unsigned)v);
    r.y = __uint_as_float((unsigned)(v >> 32));
    return r;
}

// ============================================================
// Embedding
// ============================================================
__global__ void embed_kernel(const float* __restrict__ img,
                             const float* __restrict__ rad,
                             const float* __restrict__ pos,
                             float* __restrict__ x) {
    int idx = blockIdx.x * 256 + threadIdx.x;
    int c = idx & (NC - 1);
    int r = idx >> 9;
    int b = r / T;
    int t = r - b * T;
    float val;
    if (t < 1024) {
        int hh = t >> 6, ww = t & 63;
        val = img[(((size_t)b * NC + c) * 16 + hh) * 64 + ww];
    } else {
        int tr = t - 1024;
        int hh = tr >> 4, ww = tr & 15;
        val = rad[(((size_t)b * NC + c) * 16 + hh) * 16 + ww];
    }
    x[idx] = pos[t * NC + c] + val;
}

// ============================================================
// LayerNorm
// ============================================================
__global__ void ln_kernel(const float* __restrict__ x, float* __restrict__ o,
                          const float* __restrict__ w, const float* __restrict__ bsh) {
    int r = blockIdx.x, tid = threadIdx.x;
    const float4 v = *(const float4*)(x + (size_t)r * NC + tid * 4);
    float s  = v.x + v.y + v.z + v.w;
    float sq = v.x * v.x + v.y * v.y + v.z * v.z + v.w * v.w;
    #pragma unroll
    for (int off = 16; off; off >>= 1) {
        s  += __shfl_xor_sync(0xFFFFFFFFu, s,  off);
        sq += __shfl_xor_sync(0xFFFFFFFFu, sq, off);
    }
    __shared__ float ss[4], sqs[4];
    if ((tid & 31) == 0) { ss[tid >> 5] = s; sqs[tid >> 5] = sq; }
    __syncthreads();
    s  = ss[0] + ss[1] + ss[2] + ss[3];
    sq = sqs[0] + sqs[1] + sqs[2] + sqs[3];
    float mean = s * (1.0f / NC);
    float var  = sq * (1.0f / NC) - mean * mean;
    float rstd = rsqrtf(var + 1e-5f);
    float4 wv = *(const float4*)(w + tid * 4);
    float4 bv = *(const float4*)(bsh + tid * 4);
    float4 ov;
    ov.x = (v.x - mean) * rstd * wv.x + bv.x;
    ov.y = (v.y - mean) * rstd * wv.y + bv.y;
    ov.z = (v.z - mean) * rstd * wv.z + bv.z;
    ov.w = (v.w - mean) * rstd * wv.w + bv.w;
    *(float4*)(o + (size_t)r * NC + tid * 4) = ov;
}

// ============================================================
// Final LN fused with output layout split
// ============================================================
__global__ void lnf_out_kernel(const float* __restrict__ x, float* __restrict__ out,
                               const float* __restrict__ w, const float* __restrict__ bsh) {
    int r = blockIdx.x, tid = threadIdx.x;
    int b = r / T, t = r - b * T;
    const float4 v = *(const float4*)(x + (size_t)r * NC + tid * 4);
    float s  = v.x + v.y + v.z + v.w;
    float sq = v.x * v.x + v.y * v.y + v.z * v.z + v.w * v.w;
    #pragma unroll
    for (int off = 16; off; off >>= 1) {
        s  += __shfl_xor_sync(0xFFFFFFFFu, s,  off);
        sq += __shfl_xor_sync(0xFFFFFFFFu, sq, off);
    }
    __shared__ float ss[4], sqs[4];
    if ((tid & 31) == 0) { ss[tid >> 5] = s; sqs[tid >> 5] = sq; }
    __syncthreads();
    s  = ss[0] + ss[1] + ss[2] + ss[3];
    sq = sqs[0] + sqs[1] + sqs[2] + sqs[3];
    float mean = s * (1.0f / NC);
    float var  = sq * (1.0f / NC) - mean * mean;
    float rstd = rsqrtf(var + 1e-5f);
    float4 wv = *(const float4*)(w + tid * 4);
    float4 bv = *(const float4*)(bsh + tid * 4);
    float4 ov;
    ov.x = (v.x - mean) * rstd * wv.x + bv.x;
    ov.y = (v.y - mean) * rstd * wv.y + bv.y;
    ov.z = (v.z - mean) * rstd * wv.z + bv.z;
    ov.w = (v.w - mean) * rstd * wv.w + bv.w;
    float* dst;
    if (t < 1024) dst = out + ((size_t)b * 1024 + t) * NC;
    else          dst = out + (size_t)NB * 1024 * NC + ((size_t)b * 256 + (t - 1024)) * NC;
    *(float4*)(dst + tid * 4) = ov;
}

// ============================================================
// GEMM with FFMA2: D = epi(A @ Bw + bias [+ res])
// 128x128 tile, BK=16, 256 threads, 8x8 per thread.
// A tile stored DUPLICATED in smem so the multiplicand pairs
// (a,a) come straight out of LDS.128.
// ============================================================
template <int EPI>
__global__ void __launch_bounds__(256)
gemm_kernel(const float* __restrict__ A, const float* __restrict__ Bw,
            const float* __restrict__ bias, const float* __restrict__ res,
            float* __restrict__ D, int M, int N, int K) {
    __shared__ float Asd[16][256];   // duplicated: Asd[k][2m]=Asd[k][2m+1]=A[m][k]
    __shared__ float Bs [16][128];
    int tid = threadIdx.x;
    int bm = blockIdx.y * 128;
    int bn = blockIdx.x * 128;
    int tx = tid & 15, ty = tid >> 4;

    int arow = tid >> 1;
    int acol = (tid & 1) * 8;
    int brow = tid >> 4;
    int bcol = (tid & 15) * 8;
    const float* Aptr = A  + (size_t)(bm + arow) * K + acol;
    const float* Bptr = Bw + (size_t)brow * N + bn + bcol;

    unsigned long long acc[8][4];
    #pragma unroll
    for (int i = 0; i < 8; i++)
        #pragma unroll
        for (int j = 0; j < 4; j++) acc[i][j] = 0ull;

    for (int k0 = 0; k0 < K; k0 += 16) {
        float4 a0 = *(const float4*)(Aptr);
        float4 a1 = *(const float4*)(Aptr + 4);
        float4 b0 = *(const float4*)(Bptr);
        float4 b1 = *(const float4*)(Bptr + 4);
        Aptr += 16;
        Bptr += (size_t)16 * N;
        *(float2*)&Asd[acol + 0][2 * arow] = make_float2(a0.x, a0.x);
        *(float2*)&Asd[acol + 1][2 * arow] = make_float2(a0.y, a0.y);
        *(float2*)&Asd[acol + 2][2 * arow] = make_float2(a0.z, a0.z);
        *(float2*)&Asd[acol + 3][2 * arow] = make_float2(a0.w, a0.w);
        *(float2*)&Asd[acol + 4][2 * arow] = make_float2(a1.x, a1.x);
        *(float2*)&Asd[acol + 5][2 * arow] = make_float2(a1.y, a1.y);
        *(float2*)&Asd[acol + 6][2 * arow] = make_float2(a1.z, a1.z);
        *(float2*)&Asd[acol + 7][2 * arow] = make_float2(a1.w, a1.w);
        *(float4*)&Bs[brow][bcol]     = b0;
        *(float4*)&Bs[brow][bcol + 4] = b1;
        __syncthreads();
        #pragma unroll
        for (int k = 0; k < 16; k++) {
            ulonglong2 apA = *(const ulonglong2*)&Asd[k][ty * 16];
            ulonglong2 apB = *(const ulonglong2*)&Asd[k][ty * 16 + 4];
            ulonglong2 apC = *(const ulonglong2*)&Asd[k][ty * 16 + 8];
            ulonglong2 apD = *(const ulonglong2*)&Asd[k][ty * 16 + 12];
            ulonglong2 bpA = *(const ulonglong2*)&Bs[k][tx * 8];
            ulonglong2 bpB = *(const ulonglong2*)&Bs[k][tx * 8 + 4];
            unsigned long long ad[8] = {apA.x, apA.y, apB.x, apB.y,
                                        apC.x, apC.y, apD.x, apD.y};
            unsigned long long bp[4] = {bpA.x, bpA.y, bpB.x, bpB.y};
            #pragma unroll
            for (int i = 0; i < 8; i++)
                #pragma unroll
                for (int j = 0; j < 4; j++)
                    fma2(acc[i][j], ad[i], bp[j]);
        }
        __syncthreads();
    }

    float bvals[8];
    #pragma unroll
    for (int j = 0; j < 8; j++) bvals[j] = bias[bn + tx * 8 + j];
    #pragma unroll
    for (int i = 0; i < 8; i++) {
        int m = bm + ty * 8 + i;
        float* drow = D + (size_t)m * N + bn + tx * 8;
        #pragma unroll
        for (int j2 = 0; j2 < 4; j2++) {
            float2 p = unpk(acc[i][j2]);
            float v0 = p.x + bvals[2 * j2];
            float v1 = p.y + bvals[2 * j2 + 1];
            if (EPI == 1) { v0 = fmaxf(v0, 0.0f); v1 = fmaxf(v1, 0.0f); }
            if (EPI == 2) { v0 += drow[2 * j2]; v1 += drow[2 * j2 + 1]; }
            drow[2 * j2]     = v0;
            drow[2 * j2 + 1] = v1;
        }
    }
}

// ============================================================
// Attention scores with FFMA2: S = 0.125 * Q K^T
// 64x64 tile, 4x4 per thread, Q tile duplicated.
// ============================================================
__global__ void __launch_bounds__(256)
scores_kernel(const float* __restrict__ q, const float* __restrict__ k,
              float* __restrict__ S) {
    int bh = blockIdx.z;
    int b = bh >> 3, nh = bh & 7;
    int t0 = blockIdx.y * 64, s0 = blockIdx.x * 64;
    const float* qb = q + ((size_t)b * T) * NC + nh * HD;
    const float* kb = k + ((size_t)b * T) * NC + nh * HD;
    __shared__ float Qsd[64][136];  // [d][2t] duplicated
    __shared__ float Ks [64][68];   // [d][s]
    int tid = threadIdx.x;
    int lr = tid >> 2, lc = (tid & 3) * 16;
    const float* qs = qb + (size_t)(t0 + lr) * NC + lc;
    const float* ks = kb + (size_t)(s0 + lr) * NC + lc;
    #pragma unroll
    for (int u = 0; u < 16; u += 4) {
        float4 qv = *(const float4*)(qs + u);
        float4 kv = *(const float4*)(ks + u);
        *(float2*)&Qsd[lc + u + 0][2 * lr] = make_float2(qv.x, qv.x);
        *(float2*)&Qsd[lc + u + 1][2 * lr] = make_float2(qv.y, qv.y);
        *(float2*)&Qsd[lc + u + 2][2 * lr] = make_float2(qv.z, qv.z);
        *(float2*)&Qsd[lc + u + 3][2 * lr] = make_float2(qv.w, qv.w);
        Ks[lc + u + 0][lr] = kv.x; Ks[lc + u + 1][lr] = kv.y;
        Ks[lc + u + 2][lr] = kv.z; Ks[lc + u + 3][lr] = kv.w;
    }
    __syncthreads();
    int tx = tid & 15, ty = tid >> 4;
    unsigned long long acc[4][2];
    #pragma unroll
    for (int i = 0; i < 4; i++) { acc[i][0] = 0ull; acc[i][1] = 0ull; }
    #pragma unroll 16
    for (int d = 0; d < 64; d++) {
        ulonglong2 qpA = *(const ulonglong2*)&Qsd[d][ty * 8];
        ulonglong2 qpB = *(const ulonglong2*)&Qsd[d][ty * 8 + 4];
        ulonglong2 kp  = *(const ulonglong2*)&Ks[d][tx * 4];
        unsigned long long qd[4] = {qpA.x, qpA.y, qpB.x, qpB.y};
        #pragma unroll
        for (int i = 0; i < 4; i++) {
            fma2(acc[i][0], qd[i], kp.x);
            fma2(acc[i][1], qd[i], kp.y);
        }
    }
    float* outp = S + ((size_t)bh * T + t0 + ty * 4) * T + s0 + tx * 4;
    #pragma unroll
    for (int i = 0; i < 4; i++) {
        float2 p0 = unpk(acc[i][0]);
        float2 p1 = unpk(acc[i][1]);
        *(float4*)(outp + (size_t)i * T) =
            make_float4(p0.x * 0.125f, p0.y * 0.125f, p1.x * 0.125f, p1.y * 0.125f);
    }
}

// ============================================================
// Row softmax over T=1280
// ============================================================
__global__ void softmax_kernel(float* __restrict__ S) {
    size_t row = blockIdx.x;
    float* p = S + row * (size_t)T;
    int tid = threadIdx.x;
    float vals[5];
    float mx = -1e30f;
    #pragma unroll
    for (int u = 0; u < 5; u++) { vals[u] = p[tid + u * 256]; mx = fmaxf(mx, vals[u]); }
    #pragma unroll
    for (int off = 16; off; off >>= 1) mx = fmaxf(mx, __shfl_xor_sync(0xFFFFFFFFu, mx, off));
    __shared__ float sm[8], sm2[8];
    if ((tid & 31) == 0) sm[tid >> 5] = mx;
    __syncthreads();
    float bm = sm[0];
    #pragma unroll
    for (int w = 1; w < 8; w++) bm = fmaxf(bm, sm[w]);
    float ssum = 0.0f;
    #pragma unroll
    for (int u = 0; u < 5; u++) { vals[u] = __expf(vals[u] - bm); ssum += vals[u]; }
    #pragma unroll
    for (int off = 16; off; off >>= 1) ssum += __shfl_xor_sync(0xFFFFFFFFu, ssum, off);
    if ((tid & 31) == 0) sm2[tid >> 5] = ssum;
    __syncthreads();
    float tot = sm2[0];
    #pragma unroll
    for (int w = 1; w < 8; w++) tot += sm2[w];
    float inv = 1.0f / tot;
    #pragma unroll
    for (int u = 0; u < 5; u++) p[tid + u * 256] = vals[u] * inv;
}

// ============================================================
// AV with FFMA2: Y = P @ V   (P tile duplicated)
// ============================================================
__global__ void __launch_bounds__(256)
av_kernel(const float* __restrict__ S, const float* __restrict__ v,
          float* __restrict__ y) {
    int bh = blockIdx.y;
    int b = bh >> 3, nh = bh & 7;
    int t0 = blockIdx.x * 64;
    __shared__ float Psd[64][136];  // [s][2t] duplicated
    __shared__ float Vs [64][64];   // [s][d]
    int tid = threadIdx.x;
    int tx = tid & 15, ty = tid >> 4;
    int lr = tid >> 2, lc = (tid & 3) * 16;
    const float* sbase = S + ((size_t)bh * T + t0 + lr) * T + lc;
    const float* vb = v + ((size_t)b * T) * NC + nh * HD;
    unsigned long long acc[4][2];
    #pragma unroll
    for (int i = 0; i < 4; i++) { acc[i][0] = 0ull; acc[i][1] = 0ull; }

    for (int s0 = 0; s0 < T; s0 += 64) {
        #pragma unroll
        for (int u = 0; u < 16; u += 4) {
            float4 pv = *(const float4*)(sbase + s0 + u);
            *(float2*)&Psd[lc + u + 0][2 * lr] = make_float2(pv.x, pv.x);
            *(float2*)&Psd[lc + u + 1][2 * lr] = make_float2(pv.y, pv.y);
            *(float2*)&Psd[lc + u + 2][2 * lr] = make_float2(pv.z, pv.z);
            *(float2*)&Psd[lc + u + 3][2 * lr] = make_float2(pv.w, pv.w);
            float4 vv = *(const float4*)(vb + (size_t)(s0 + lr) * NC + lc + u);
            *(float4*)&Vs[lr][lc + u] = vv;
        }
        __syncthreads();
        #pragma unroll 16
        for (int s = 0; s < 64; s++) {
            ulonglong2 ppA = *(const ulonglong2*)&Psd[s][ty * 8];
            ulonglong2 ppB = *(const ulonglong2*)&Psd[s][ty * 8 + 4];
            ulonglong2 vp  = *(const ulonglong2*)&Vs[s][tx * 4];
            unsigned long long pd[4] = {ppA.x, ppA.y, ppB.x, ppB.y};
            #pragma unroll
            for (int i = 0; i < 4; i++) {
                fma2(acc[i][0], pd[i], vp.x);
                fma2(acc[i][1], pd[i], vp.y);
            }
        }
        __syncthreads();
    }
    #pragma unroll
    for (int i = 0; i < 4; i++) {
        float2 p0 = unpk(acc[i][0]);
        float2 p1 = unpk(acc[i][1]);
        float* dst = y + ((size_t)b * T + t0 + ty * 4 + i) * NC + nh * HD + tx * 4;
        *(float4*)dst = make_float4(p0.x, p0.y, p1.x, p1.y);
    }
}

// ============================================================
// host launch
// ============================================================
extern "C" void kernel_launch(void* const* d_in, const int* in_sizes, int n_in,
                              void* d_out, int out_size) {
    const float* img  = (const float*)d_in[0];
    const float* rad  = (const float*)d_in[1];
    const float* pos  = (const float*)d_in[2];
    const float* ln1w = (const float*)d_in[3];
    const float* ln1b = (const float*)d_in[4];
    const float* Wq   = (const float*)d_in[5];
    const float* bq   = (const float*)d_in[6];
    const float* Wk   = (const float*)d_in[7];
    const float* bk   = (const float*)d_in[8];
    const float* Wv   = (const float*)d_in[9];
    const float* bv   = (const float*)d_in[10];
    const float* Wo   = (const float*)d_in[11];
    const float* bo   = (const float*)d_in[12];
    const float* ln2w = (const float*)d_in[13];
    const float* ln2b = (const float*)d_in[14];
    const float* W1   = (const float*)d_in[15];
    const float* b1   = (const float*)d_in[16];
    const float* W2   = (const float*)d_in[17];
    const float* b2   = (const float*)d_in[18];
    const float* lnfw = (const float*)d_in[19];
    const float* lnfb = (const float*)d_in[20];
    float* out = (float*)d_out;

    float *x, *h, *q, *k, *v, *y, *ff, *s;
    cudaGetSymbolAddress((void**)&x,  g_x);
    cudaGetSymbolAddress((void**)&h,  g_h);
    cudaGetSymbolAddress((void**)&q,  g_q);
    cudaGetSymbolAddress((void**)&k,  g_k);
    cudaGetSymbolAddress((void**)&v,  g_v);
    cudaGetSymbolAddress((void**)&y,  g_y);
    cudaGetSymbolAddress((void**)&ff, g_ff);
    cudaGetSymbolAddress((void**)&s,  g_s);

    embed_kernel<<<(MROWS * NC) / 256, 256>>>(img, rad, pos, x);

    dim3 gC(NC / 128, MROWS / 128);
    dim3 gF(FF / 128, MROWS / 128);
    dim3 gSc(T / 64, T / 64, NB * NHEADS);
    dim3 gAv(T / 64, NB * NHEADS);

    for (int i = 0; i < LAYERS; i++) {
        size_t wOff = (size_t)i * NC * NC;
        ln_kernel<<<MROWS, 128>>>(x, h, ln1w + i * NC, ln1b + i * NC);
        gemm_kernel<0><<<gC, 256>>>(h, Wq + wOff, bq + i * NC, nullptr, q, MROWS, NC, NC);
        gemm_kernel<0><<<gC, 256>>>(h, Wk + wOff, bk + i * NC, nullptr, k, MROWS, NC, NC);
        gemm_kernel<0><<<gC, 256>>>(h, Wv + wOff, bv + i * NC, nullptr, v, MROWS, NC, NC);
        scores_kernel<<<gSc, 256>>>(q, k, s);
        softmax_kernel<<<NB * NHEADS * T, 256>>>(s);
        av_kernel<<<gAv, 256>>>(s, v, y);
        gemm_kernel<2><<<gC, 256>>>(y, Wo + wOff, bo + i * NC, x, x, MROWS, NC, NC);
        ln_kernel<<<MROWS, 128>>>(x, h, ln2w + i * NC, ln2b + i * NC);
        gemm_kernel<1><<<gF, 256>>>(h, W1 + (size_t)i * NC * FF, b1 + i * FF, nullptr,
                                    ff, MROWS, FF, NC);
        gemm_kernel<2><<<gC, 256>>>(ff, W2 + (size_t)i * FF * NC, b2 + i * NC, x, x,
                                    MROWS, NC, FF);
    }
    lnf_out_kernel<<<MROWS, 128>>>(x, out, lnfw, lnfb);
}

// round 6
// speedup vs baseline: 2.9590x; 2.9590x over previous
#include <cuda_runtime.h>
#include <cstddef>
#include <cstdint>

// ----- problem dims -----
constexpr int NB = 16;
constexpr int NC = 512;
constexpr int NHEADS = 8;
constexpr int HD = 64;
constexpr int FF = 2048;
constexpr int LAYERS = 6;
constexpr int T = 1280;
constexpr int MROWS = NB * T; // 20480

// ----- scratch -----
__device__ float g_x [(size_t)MROWS * NC];
__device__ float g_h [(size_t)MROWS * NC];
__device__ float g_q [(size_t)MROWS * NC];
__device__ float g_k [(size_t)MROWS * NC];
__device__ float g_v [(size_t)MROWS * NC];
__device__ float g_y [(size_t)MROWS * NC];
__device__ float g_ff[(size_t)MROWS * FF];
__device__ float g_s [(size_t)NB * NHEADS * T * T];

// ----- tf32 helpers -----
__device__ __forceinline__ unsigned f2tf(float f) {
    unsigned u;
    asm("cvt.rna.tf32.f32 %0, %1;" : "=r"(u) : "f"(f));
    return u;
}
__device__ __forceinline__ void mma_tf32(float c[4], const unsigned a[4], const unsigned b[2]) {
    asm("mma.sync.aligned.m16n8k8.row.col.f32.tf32.tf32.f32 "
        "{%0,%1,%2,%3},{%4,%5,%6,%7},{%8,%9},{%0,%1,%2,%3};"
        : "+f"(c[0]), "+f"(c[1]), "+f"(c[2]), "+f"(c[3])
        : "r"(a[0]), "r"(a[1]), "r"(a[2]), "r"(a[3]), "r"(b[0]), "r"(b[1]));
}

// ============================================================
// Embedding
// ============================================================
__global__ void embed_kernel(const float* __restrict__ img,
                             const float* __restrict__ rad,
                             const float* __restrict__ pos,
                             float* __restrict__ x) {
    int idx = blockIdx.x * 256 + threadIdx.x;
    int c = idx & (NC - 1);
    int r = idx >> 9;
    int b = r / T;
    int t = r - b * T;
    float val;
    if (t < 1024) {
        int hh = t >> 6, ww = t & 63;
        val = img[(((size_t)b * NC + c) * 16 + hh) * 64 + ww];
    } else {
        int tr = t - 1024;
        int hh = tr >> 4, ww = tr & 15;
        val = rad[(((size_t)b * NC + c) * 16 + hh) * 16 + ww];
    }
    x[idx] = pos[t * NC + c] + val;
}

// ============================================================
// LayerNorm
// ============================================================
__global__ void ln_kernel(const float* __restrict__ x, float* __restrict__ o,
                          const float* __restrict__ w, const float* __restrict__ bsh) {
    int r = blockIdx.x, tid = threadIdx.x;
    const float4 v = *(const float4*)(x + (size_t)r * NC + tid * 4);
    float s  = v.x + v.y + v.z + v.w;
    float sq = v.x * v.x + v.y * v.y + v.z * v.z + v.w * v.w;
    #pragma unroll
    for (int off = 16; off; off >>= 1) {
        s  += __shfl_xor_sync(0xFFFFFFFFu, s,  off);
        sq += __shfl_xor_sync(0xFFFFFFFFu, sq, off);
    }
    __shared__ float ss[4], sqs[4];
    if ((tid & 31) == 0) { ss[tid >> 5] = s; sqs[tid >> 5] = sq; }
    __syncthreads();
    s  = ss[0] + ss[1] + ss[2] + ss[3];
    sq = sqs[0] + sqs[1] + sqs[2] + sqs[3];
    float mean = s * (1.0f / NC);
    float var  = sq * (1.0f / NC) - mean * mean;
    float rstd = rsqrtf(var + 1e-5f);
    float4 wv = *(const float4*)(w + tid * 4);
    float4 bv = *(const float4*)(bsh + tid * 4);
    float4 ov;
    ov.x = (v.x - mean) * rstd * wv.x + bv.x;
    ov.y = (v.y - mean) * rstd * wv.y + bv.y;
    ov.z = (v.z - mean) * rstd * wv.z + bv.z;
    ov.w = (v.w - mean) * rstd * wv.w + bv.w;
    *(float4*)(o + (size_t)r * NC + tid * 4) = ov;
}

// ============================================================
// Final LN fused with output layout split
// ============================================================
__global__ void lnf_out_kernel(const float* __restrict__ x, float* __restrict__ out,
                               const float* __restrict__ w, const float* __restrict__ bsh) {
    int r = blockIdx.x, tid = threadIdx.x;
    int b = r / T, t = r - b * T;
    const float4 v = *(const float4*)(x + (size_t)r * NC + tid * 4);
    float s  = v.x + v.y + v.z + v.w;
    float sq = v.x * v.x + v.y * v.y + v.z * v.z + v.w * v.w;
    #pragma unroll
    for (int off = 16; off; off >>= 1) {
        s  += __shfl_xor_sync(0xFFFFFFFFu, s,  off);
        sq += __shfl_xor_sync(0xFFFFFFFFu, sq, off);
    }
    __shared__ float ss[4], sqs[4];
    if ((tid & 31) == 0) { ss[tid >> 5] = s; sqs[tid >> 5] = sq; }
    __syncthreads();
    s  = ss[0] + ss[1] + ss[2] + ss[3];
    sq = sqs[0] + sqs[1] + sqs[2] + sqs[3];
    float mean = s * (1.0f / NC);
    float var  = sq * (1.0f / NC) - mean * mean;
    float rstd = rsqrtf(var + 1e-5f);
    float4 wv = *(const float4*)(w + tid * 4);
    float4 bv = *(const float4*)(bsh + tid * 4);
    float4 ov;
    ov.x = (v.x - mean) * rstd * wv.x + bv.x;
    ov.y = (v.y - mean) * rstd * wv.y + bv.y;
    ov.z = (v.z - mean) * rstd * wv.z + bv.z;
    ov.w = (v.w - mean) * rstd * wv.w + bv.w;
    float* dst;
    if (t < 1024) dst = out + ((size_t)b * 1024 + t) * NC;
    else          dst = out + (size_t)NB * 1024 * NC + ((size_t)b * 256 + (t - 1024)) * NC;
    *(float4*)(dst + tid * 4) = ov;
}

// ============================================================
// TF32 tensor-core GEMM: D = epi(A[MxK] @ Bw[KxN] + bias)
// 128x128 block tile, BK=32, 256 threads = 8 warps (2m x 4n),
// warp tile 64x32 -> 4x4 mma tiles of m16n8k8.
// EPI: 0 = bias, 1 = bias+relu, 2 = bias+residual(D aliases x)
// ============================================================
template <int EPI>
__global__ void __launch_bounds__(256)
gemm_tf32(const float* __restrict__ A, const float* __restrict__ Bw,
          const float* __restrict__ bias, float* __restrict__ D,
          int M, int N, int K) {
    __shared__ unsigned As[32][136];   // [k][m], tf32 bits
    __shared__ unsigned Bs[32][136];   // [k][n], tf32 bits
    int tid = threadIdx.x;
    int lane = tid & 31;
    int wid = tid >> 5;
    int warpM = wid & 1;        // 0..1
    int warpN = wid >> 1;       // 0..3
    int g = lane >> 2;          // groupID 0..7
    int tg = lane & 3;          // thread-in-group 0..3
    int bm = blockIdx.y * 128;
    int bn = blockIdx.x * 128;

    int arow = tid >> 1;           // m 0..127
    int acb  = (tid & 1) * 16;     // k base 0/16
    int brow = tid >> 5;           // k 0..7 (+8u)
    int bcol = (tid & 31) * 4;     // n 0..124

    const float* Aptr = A  + (size_t)(bm + arow) * K + acb;
    const float* Bptr = Bw + (size_t)brow * N + bn + bcol;

    float acc[4][4][4];
    #pragma unroll
    for (int i = 0; i < 4; i++)
        #pragma unroll
        for (int j = 0; j < 4; j++)
            #pragma unroll
            for (int e = 0; e < 4; e++) acc[i][j][e] = 0.0f;

    for (int k0 = 0; k0 < K; k0 += 32) {
        // stage A (transposed) and B
        #pragma unroll
        for (int u = 0; u < 4; u++) {
            float4 av = *(const float4*)(Aptr + u * 4);
            As[acb + u * 4 + 0][arow] = f2tf(av.x);
            As[acb + u * 4 + 1][arow] = f2tf(av.y);
            As[acb + u * 4 + 2][arow] = f2tf(av.z);
            As[acb + u * 4 + 3][arow] = f2tf(av.w);
        }
        #pragma unroll
        for (int u = 0; u < 4; u++) {
            float4 bv = *(const float4*)(Bptr + (size_t)u * 8 * N);
            uint4 bt;
            bt.x = f2tf(bv.x); bt.y = f2tf(bv.y);
            bt.z = f2tf(bv.z); bt.w = f2tf(bv.w);
            *(uint4*)&Bs[brow + u * 8][bcol] = bt;
        }
        Aptr += 32;
        Bptr += (size_t)32 * N;
        __syncthreads();

        #pragma unroll
        for (int ks = 0; ks < 4; ks++) {
            int kk = ks * 8;
            unsigned af[4][4], bf[4][2];
            #pragma unroll
            for (int mt = 0; mt < 4; mt++) {
                int m = warpM * 64 + mt * 16 + g;
                af[mt][0] = As[kk + tg][m];
                af[mt][1] = As[kk + tg][m + 8];
                af[mt][2] = As[kk + 4 + tg][m];
                af[mt][3] = As[kk + 4 + tg][m + 8];
            }
            #pragma unroll
            for (int nt = 0; nt < 4; nt++) {
                int n = warpN * 32 + nt * 8 + g;
                bf[nt][0] = Bs[kk + tg][n];
                bf[nt][1] = Bs[kk + 4 + tg][n];
            }
            #pragma unroll
            for (int mt = 0; mt < 4; mt++)
                #pragma unroll
                for (int nt = 0; nt < 4; nt++)
                    mma_tf32(acc[mt][nt], af[mt], bf[nt]);
        }
        __syncthreads();
    }

    // epilogue
    #pragma unroll
    for (int mt = 0; mt < 4; mt++) {
        int row0 = bm + warpM * 64 + mt * 16 + g;
        #pragma unroll
        for (int nt = 0; nt < 4; nt++) {
            int col = bn + warpN * 32 + nt * 8 + 2 * tg;
            float b0 = bias[col], b1 = bias[col + 1];
            float* d0 = D + (size_t)row0 * N + col;
            float* d1 = D + (size_t)(row0 + 8) * N + col;
            float v00 = acc[mt][nt][0] + b0, v01 = acc[mt][nt][1] + b1;
            float v10 = acc[mt][nt][2] + b0, v11 = acc[mt][nt][3] + b1;
            if (EPI == 1) {
                v00 = fmaxf(v00, 0.0f); v01 = fmaxf(v01, 0.0f);
                v10 = fmaxf(v10, 0.0f); v11 = fmaxf(v11, 0.0f);
            }
            if (EPI == 2) {
                float2 r0 = *(float2*)d0, r1 = *(float2*)d1;
                v00 += r0.x; v01 += r0.y; v10 += r1.x; v11 += r1.y;
            }
            *(float2*)d0 = make_float2(v00, v01);
            *(float2*)d1 = make_float2(v10, v11);
        }
    }
}

// ============================================================
// TF32 scores: S[bh,t,s] = 0.125 * Q K^T   (per b,h; K=64)
// 128x128 tile, same warp layout as gemm_tf32, 2 k-stages.
// ============================================================
__global__ void __launch_bounds__(256)
scores_tf32(const float* __restrict__ q, const float* __restrict__ k,
            float* __restrict__ S) {
    __shared__ unsigned As[32][136];   // [d][t]
    __shared__ unsigned Bs[32][136];   // [d][s]
    int tid = threadIdx.x;
    int lane = tid & 31;
    int wid = tid >> 5;
    int warpM = wid & 1, warpN = wid >> 1;
    int g = lane >> 2, tg = lane & 3;
    int bh = blockIdx.z;
    int b = bh >> 3, nh = bh & 7;
    int t0 = blockIdx.y * 128, s0 = blockIdx.x * 128;
    const float* qb = q + ((size_t)b * T) * NC + nh * HD;
    const float* kb = k + ((size_t)b * T) * NC + nh * HD;

    int arow = tid >> 1;
    int acb  = (tid & 1) * 16;

    float acc[4][4][4];
    #pragma unroll
    for (int i = 0; i < 4; i++)
        #pragma unroll
        for (int j = 0; j < 4; j++)
            #pragma unroll
            for (int e = 0; e < 4; e++) acc[i][j][e] = 0.0f;

    for (int k0 = 0; k0 < 64; k0 += 32) {
        #pragma unroll
        for (int u = 0; u < 4; u++) {
            float4 qv = *(const float4*)(qb + (size_t)(t0 + arow) * NC + k0 + acb + u * 4);
            As[acb + u * 4 + 0][arow] = f2tf(qv.x);
            As[acb + u * 4 + 1][arow] = f2tf(qv.y);
            As[acb + u * 4 + 2][arow] = f2tf(qv.z);
            As[acb + u * 4 + 3][arow] = f2tf(qv.w);
            float4 kv = *(const float4*)(kb + (size_t)(s0 + arow) * NC + k0 + acb + u * 4);
            Bs[acb + u * 4 + 0][arow] = f2tf(kv.x);
            Bs[acb + u * 4 + 1][arow] = f2tf(kv.y);
            Bs[acb + u * 4 + 2][arow] = f2tf(kv.z);
            Bs[acb + u * 4 + 3][arow] = f2tf(kv.w);
        }
        __syncthreads();
        #pragma unroll
        for (int ks = 0; ks < 4; ks++) {
            int kk = ks * 8;
            unsigned af[4][4], bf[4][2];
            #pragma unroll
            for (int mt = 0; mt < 4; mt++) {
                int m = warpM * 64 + mt * 16 + g;
                af[mt][0] = As[kk + tg][m];
                af[mt][1] = As[kk + tg][m + 8];
                af[mt][2] = As[kk + 4 + tg][m];
                af[mt][3] = As[kk + 4 + tg][m + 8];
            }
            #pragma unroll
            for (int nt = 0; nt < 4; nt++) {
                int n = warpN * 32 + nt * 8 + g;
                bf[nt][0] = Bs[kk + tg][n];
                bf[nt][1] = Bs[kk + 4 + tg][n];
            }
            #pragma unroll
            for (int mt = 0; mt < 4; mt++)
                #pragma unroll
                for (int nt = 0; nt < 4; nt++)
                    mma_tf32(acc[mt][nt], af[mt], bf[nt]);
        }
        __syncthreads();
    }

    float* Sb = S + (size_t)bh * T * T;
    #pragma unroll
    for (int mt = 0; mt < 4; mt++) {
        int row0 = t0 + warpM * 64 + mt * 16 + g;
        #pragma unroll
        for (int nt = 0; nt < 4; nt++) {
            int col = s0 + warpN * 32 + nt * 8 + 2 * tg;
            *(float2*)(Sb + (size_t)row0 * T + col) =
                make_float2(acc[mt][nt][0] * 0.125f, acc[mt][nt][1] * 0.125f);
            *(float2*)(Sb + (size_t)(row0 + 8) * T + col) =
                make_float2(acc[mt][nt][2] * 0.125f, acc[mt][nt][3] * 0.125f);
        }
    }
}

// ============================================================
// Row softmax over T=1280
// ============================================================
__global__ void softmax_kernel(float* __restrict__ S) {
    size_t row = blockIdx.x;
    float* p = S + row * (size_t)T;
    int tid = threadIdx.x;
    float vals[5];
    float mx = -1e30f;
    #pragma unroll
    for (int u = 0; u < 5; u++) { vals[u] = p[tid + u * 256]; mx = fmaxf(mx, vals[u]); }
    #pragma unroll
    for (int off = 16; off; off >>= 1) mx = fmaxf(mx, __shfl_xor_sync(0xFFFFFFFFu, mx, off));
    __shared__ float sm[8], sm2[8];
    if ((tid & 31) == 0) sm[tid >> 5] = mx;
    __syncthreads();
    float bm = sm[0];
    #pragma unroll
    for (int w = 1; w < 8; w++) bm = fmaxf(bm, sm[w]);
    float ssum = 0.0f;
    #pragma unroll
    for (int u = 0; u < 5; u++) { vals[u] = __expf(vals[u] - bm); ssum += vals[u]; }
    #pragma unroll
    for (int off = 16; off; off >>= 1) ssum += __shfl_xor_sync(0xFFFFFFFFu, ssum, off);
    if ((tid & 31) == 0) sm2[tid >> 5] = ssum;
    __syncthreads();
    float tot = sm2[0];
    #pragma unroll
    for (int w = 1; w < 8; w++) tot += sm2[w];
    float inv = 1.0f / tot;
    #pragma unroll
    for (int u = 0; u < 5; u++) p[tid + u * 256] = vals[u] * inv;
}

// ============================================================
// TF32 AV: Y = P @ V  (per b,h; M=1280, N=64, K=1280)
// 128x64 tile, 8 warps (4m x 2n), warp 32x32 -> 2x4 mma tiles.
// ============================================================
__global__ void __launch_bounds__(256)
av_tf32(const float* __restrict__ S, const float* __restrict__ v,
        float* __restrict__ y) {
    __shared__ unsigned Ps[32][136];   // [s][t]
    __shared__ unsigned Vs[32][72];    // [s][d]
    int tid = threadIdx.x;
    int lane = tid & 31;
    int wid = tid >> 5;
    int warpM = wid & 3;     // 0..3
    int warpN = wid >> 2;    // 0..1
    int g = lane >> 2, tg = lane & 3;
    int bh = blockIdx.y;
    int b = bh >> 3, nh = bh & 7;
    int t0 = blockIdx.x * 128;
    const float* Pb = S + (size_t)bh * T * T;
    const float* vb = v + ((size_t)b * T) * NC + nh * HD;

    int arow = tid >> 1;          // t 0..127
    int acb  = (tid & 1) * 16;    // s base
    int vrow = tid >> 4;          // k 0..15 (+16u)
    int vcol = (tid & 15) * 4;    // d 0..60

    float acc[2][4][4];
    #pragma unroll
    for (int i = 0; i < 2; i++)
        #pragma unroll
        for (int j = 0; j < 4; j++)
            #pragma unroll
            for (int e = 0; e < 4; e++) acc[i][j][e] = 0.0f;

    for (int k0 = 0; k0 < T; k0 += 32) {
        #pragma unroll
        for (int u = 0; u < 4; u++) {
            float4 pv = *(const float4*)(Pb + (size_t)(t0 + arow) * T + k0 + acb + u * 4);
            Ps[acb + u * 4 + 0][arow] = f2tf(pv.x);
            Ps[acb + u * 4 + 1][arow] = f2tf(pv.y);
            Ps[acb + u * 4 + 2][arow] = f2tf(pv.z);
            Ps[acb + u * 4 + 3][arow] = f2tf(pv.w);
        }
        #pragma unroll
        for (int u = 0; u < 2; u++) {
            float4 vv = *(const float4*)(vb + (size_t)(k0 + vrow + u * 16) * NC + vcol);
            uint4 vt;
            vt.x = f2tf(vv.x); vt.y = f2tf(vv.y);
            vt.z = f2tf(vv.z); vt.w = f2tf(vv.w);
            *(uint4*)&Vs[vrow + u * 16][vcol] = vt;
        }
        __syncthreads();
        #pragma unroll
        for (int ks = 0; ks < 4; ks++) {
            int kk = ks * 8;
            unsigned af[2][4], bf[4][2];
            #pragma unroll
            for (int mt = 0; mt < 2; mt++) {
                int m = warpM * 32 + mt * 16 + g;
                af[mt][0] = Ps[kk + tg][m];
                af[mt][1] = Ps[kk + tg][m + 8];
                af[mt][2] = Ps[kk + 4 + tg][m];
                af[mt][3] = Ps[kk + 4 + tg][m + 8];
            }
            #pragma unroll
            for (int nt = 0; nt < 4; nt++) {
                int n = warpN * 32 + nt * 8 + g;
                bf[nt][0] = Vs[kk + tg][n];
                bf[nt][1] = Vs[kk + 4 + tg][n];
            }
            #pragma unroll
            for (int mt = 0; mt < 2; mt++)
                #pragma unroll
                for (int nt = 0; nt < 4; nt++)
                    mma_tf32(acc[mt][nt], af[mt], bf[nt]);
        }
        __syncthreads();
    }

    #pragma unroll
    for (int mt = 0; mt < 2; mt++) {
        int row0 = t0 + warpM * 32 + mt * 16 + g;
        #pragma unroll
        for (int nt = 0; nt < 4; nt++) {
            int col = warpN * 32 + nt * 8 + 2 * tg;
            float* d0 = y + ((size_t)b * T + row0) * NC + nh * HD + col;
            float* d1 = y + ((size_t)b * T + row0 + 8) * NC + nh * HD + col;
            *(float2*)d0 = make_float2(acc[mt][nt][0], acc[mt][nt][1]);
            *(float2*)d1 = make_float2(acc[mt][nt][2], acc[mt][nt][3]);
        }
    }
}

// ============================================================
// host launch
// ============================================================
extern "C" void kernel_launch(void* const* d_in, const int* in_sizes, int n_in,
                              void* d_out, int out_size) {
    const float* img  = (const float*)d_in[0];
    const float* rad  = (const float*)d_in[1];
    const float* pos  = (const float*)d_in[2];
    const float* ln1w = (const float*)d_in[3];
    const float* ln1b = (const float*)d_in[4];
    const float* Wq   = (const float*)d_in[5];
    const float* bq   = (const float*)d_in[6];
    const float* Wk   = (const float*)d_in[7];
    const float* bk   = (const float*)d_in[8];
    const float* Wv   = (const float*)d_in[9];
    const float* bv   = (const float*)d_in[10];
    const float* Wo   = (const float*)d_in[11];
    const float* bo   = (const float*)d_in[12];
    const float* ln2w = (const float*)d_in[13];
    const float* ln2b = (const float*)d_in[14];
    const float* W1   = (const float*)d_in[15];
    const float* b1   = (const float*)d_in[16];
    const float* W2   = (const float*)d_in[17];
    const float* b2   = (const float*)d_in[18];
    const float* lnfw = (const float*)d_in[19];
    const float* lnfb = (const float*)d_in[20];
    float* out = (float*)d_out;

    float *x, *h, *q, *k, *v, *y, *ff, *s;
    cudaGetSymbolAddress((void**)&x,  g_x);
    cudaGetSymbolAddress((void**)&h,  g_h);
    cudaGetSymbolAddress((void**)&q,  g_q);
    cudaGetSymbolAddress((void**)&k,  g_k);
    cudaGetSymbolAddress((void**)&v,  g_v);
    cudaGetSymbolAddress((void**)&y,  g_y);
    cudaGetSymbolAddress((void**)&ff, g_ff);
    cudaGetSymbolAddress((void**)&s,  g_s);

    embed_kernel<<<(MROWS * NC) / 256, 256>>>(img, rad, pos, x);

    dim3 gC(NC / 128, MROWS / 128);          // (4, 160)
    dim3 gF(FF / 128, MROWS / 128);          // (16, 160)
    dim3 gSc(T / 128, T / 128, NB * NHEADS); // (10, 10, 128)
    dim3 gAv(T / 128, NB * NHEADS);          // (10, 128)

    for (int i = 0; i < LAYERS; i++) {
        size_t wOff = (size_t)i * NC * NC;
        ln_kernel<<<MROWS, 128>>>(x, h, ln1w + i * NC, ln1b + i * NC);
        gemm_tf32<0><<<gC, 256>>>(h, Wq + wOff, bq + i * NC, q, MROWS, NC, NC);
        gemm_tf32<0><<<gC, 256>>>(h, Wk + wOff, bk + i * NC, k, MROWS, NC, NC);
        gemm_tf32<0><<<gC, 256>>>(h, Wv + wOff, bv + i * NC, v, MROWS, NC, NC);
        scores_tf32<<<gSc, 256>>>(q, k, s);
        softmax_kernel<<<NB * NHEADS * T, 256>>>(s);
        av_tf32<<<gAv, 256>>>(s, v, y);
        gemm_tf32<2><<<gC, 256>>>(y, Wo + wOff, bo + i * NC, x, MROWS, NC, NC);
        ln_kernel<<<MROWS, 128>>>(x, h, ln2w + i * NC, ln2b + i * NC);
        gemm_tf32<1><<<gF, 256>>>(h, W1 + (size_t)i * NC * FF, b1 + i * FF, ff,
                                  MROWS, FF, NC);
        gemm_tf32<2><<<gC, 256>>>(ff, W2 + (size_t)i * FF * NC, b2 + i * NC, x,
                                  MROWS, NC, FF);
    }
    lnf_out_kernel<<<MROWS, 128>>>(x, out, lnfw, lnfb);
}

// round 8
// speedup vs baseline: 3.0701x; 1.0376x over previous
#include <cuda_runtime.h>
#include <cstddef>
#include <cstdint>

// ----- problem dims -----
constexpr int NB = 16;
constexpr int NC = 512;
constexpr int NHEADS = 8;
constexpr int HD = 64;
constexpr int FF = 2048;
constexpr int LAYERS = 6;
constexpr int T = 1280;
constexpr int MROWS = NB * T; // 20480

// ----- scratch -----
__device__ float g_x [(size_t)MROWS * NC];
__device__ float g_h [(size_t)MROWS * NC];
__device__ float g_q [(size_t)MROWS * NC];
__device__ float g_k [(size_t)MROWS * NC];
__device__ float g_v [(size_t)MROWS * NC];
__device__ float g_y [(size_t)MROWS * NC];
__device__ float g_ff[(size_t)MROWS * FF];
__device__ float g_s [(size_t)NB * NHEADS * T * T];

// ----- mma / cp.async helpers -----
__device__ __forceinline__ void mma_tf32(float c[4], const unsigned a[4], const unsigned b[2]) {
    asm("mma.sync.aligned.m16n8k8.row.col.f32.tf32.tf32.f32 "
        "{%0,%1,%2,%3},{%4,%5,%6,%7},{%8,%9},{%0,%1,%2,%3};"
        : "+f"(c[0]), "+f"(c[1]), "+f"(c[2]), "+f"(c[3])
        : "r"(a[0]), "r"(a[1]), "r"(a[2]), "r"(a[3]), "r"(b[0]), "r"(b[1]));
}
__device__ __forceinline__ void cp16(uint32_t dst, const float* src) {
    asm volatile("cp.async.cg.shared.global [%0], [%1], 16;" :: "r"(dst), "l"(src));
}
#define CP_COMMIT() asm volatile("cp.async.commit_group;")
#define CP_WAIT1()  asm volatile("cp.async.wait_group 1;")
__device__ __forceinline__ unsigned fbits(float f) { return __float_as_uint(f); }

// ============================================================
// Embedding
// ============================================================
__global__ void embed_kernel(const float* __restrict__ img,
                             const float* __restrict__ rad,
                             const float* __restrict__ pos,
                             float* __restrict__ x) {
    int idx = blockIdx.x * 256 + threadIdx.x;
    int c = idx & (NC - 1);
    int r = idx >> 9;
    int b = r / T;
    int t = r - b * T;
    float val;
    if (t < 1024) {
        int hh = t >> 6, ww = t & 63;
        val = img[(((size_t)b * NC + c) * 16 + hh) * 64 + ww];
    } else {
        int tr = t - 1024;
        int hh = tr >> 4, ww = tr & 15;
        val = rad[(((size_t)b * NC + c) * 16 + hh) * 16 + ww];
    }
    x[idx] = pos[t * NC + c] + val;
}

// ============================================================
// LayerNorm
// ============================================================
__global__ void ln_kernel(const float* __restrict__ x, float* __restrict__ o,
                          const float* __restrict__ w, const float* __restrict__ bsh) {
    int r = blockIdx.x, tid = threadIdx.x;
    const float4 v = *(const float4*)(x + (size_t)r * NC + tid * 4);
    float s  = v.x + v.y + v.z + v.w;
    float sq = v.x * v.x + v.y * v.y + v.z * v.z + v.w * v.w;
    #pragma unroll
    for (int off = 16; off; off >>= 1) {
        s  += __shfl_xor_sync(0xFFFFFFFFu, s,  off);
        sq += __shfl_xor_sync(0xFFFFFFFFu, sq, off);
    }
    __shared__ float ss[4], sqs[4];
    if ((tid & 31) == 0) { ss[tid >> 5] = s; sqs[tid >> 5] = sq; }
    __syncthreads();
    s  = ss[0] + ss[1] + ss[2] + ss[3];
    sq = sqs[0] + sqs[1] + sqs[2] + sqs[3];
    float mean = s * (1.0f / NC);
    float var  = sq * (1.0f / NC) - mean * mean;
    float rstd = rsqrtf(var + 1e-5f);
    float4 wv = *(const float4*)(w + tid * 4);
    float4 bv = *(const float4*)(bsh + tid * 4);
    float4 ov;
    ov.x = (v.x - mean) * rstd * wv.x + bv.x;
    ov.y = (v.y - mean) * rstd * wv.y + bv.y;
    ov.z = (v.z - mean) * rstd * wv.z + bv.z;
    ov.w = (v.w - mean) * rstd * wv.w + bv.w;
    *(float4*)(o + (size_t)r * NC + tid * 4) = ov;
}

// ============================================================
// Final LN fused with output layout split
// ============================================================
__global__ void lnf_out_kernel(const float* __restrict__ x, float* __restrict__ out,
                               const float* __restrict__ w, const float* __restrict__ bsh) {
    int r = blockIdx.x, tid = threadIdx.x;
    int b = r / T, t = r - b * T;
    const float4 v = *(const float4*)(x + (size_t)r * NC + tid * 4);
    float s  = v.x + v.y + v.z + v.w;
    float sq = v.x * v.x + v.y * v.y + v.z * v.z + v.w * v.w;
    #pragma unroll
    for (int off = 16; off; off >>= 1) {
        s  += __shfl_xor_sync(0xFFFFFFFFu, s,  off);
        sq += __shfl_xor_sync(0xFFFFFFFFu, sq, off);
    }
    __shared__ float ss[4], sqs[4];
    if ((tid & 31) == 0) { ss[tid >> 5] = s; sqs[tid >> 5] = sq; }
    __syncthreads();
    s  = ss[0] + ss[1] + ss[2] + ss[3];
    sq = sqs[0] + sqs[1] + sqs[2] + sqs[3];
    float mean = s * (1.0f / NC);
    float var  = sq * (1.0f / NC) - mean * mean;
    float rstd = rsqrtf(var + 1e-5f);
    float4 wv = *(const float4*)(w + tid * 4);
    float4 bv = *(const float4*)(bsh + tid * 4);
    float4 ov;
    ov.x = (v.x - mean) * rstd * wv.x + bv.x;
    ov.y = (v.y - mean) * rstd * wv.y + bv.y;
    ov.z = (v.z - mean) * rstd * wv.z + bv.z;
    ov.w = (v.w - mean) * rstd * wv.w + bv.w;
    float* dst;
    if (t < 1024) dst = out + ((size_t)b * 1024 + t) * NC;
    else          dst = out + (size_t)NB * 1024 * NC + ((size_t)b * 256 + (t - 1024)) * NC;
    *(float4*)(dst + tid * 4) = ov;
}

// ============================================================
// TF32 GEMM, cp.async 2-stage pipeline, raw-f32 operands.
// 128x128 tile, BK=32, 8 warps (2m x 4n), warp 64x32.
// As: [2][128][36] (bank = 4g+tg, conflict-free)
// Bs: [2][32][136] (bank = 8tg+g, conflict-free)
// EPI: 0 bias, 1 bias+relu, 2 bias+residual (D aliases x)
// ============================================================
constexpr int GEMM_SMEM = (2 * 128 * 36 + 2 * 32 * 136) * 4;   // 71680 B

template <int EPI>
__global__ void __launch_bounds__(256, 2)
gemm_tf32(const float* __restrict__ A, const float* __restrict__ Bw,
          const float* __restrict__ bias, float* __restrict__ D,
          int M, int N, int K) {
    extern __shared__ float sm[];
    float* As = sm;                   // 2*128*36
    float* Bs = sm + 2 * 128 * 36;    // 2*32*136
    int tid = threadIdx.x;
    int lane = tid & 31, wid = tid >> 5;
    int warpM = wid & 1, warpN = wid >> 1;
    int g = lane >> 2, tg = lane & 3;
    int bm = blockIdx.y * 128, bn = blockIdx.x * 128;

    int arow = tid >> 1, acol = (tid & 1) * 16;
    int brow = tid >> 3, bcol = (tid & 7) * 16;
    const float* Ag = A  + (size_t)(bm + arow) * K + acol;
    const float* Bg = Bw + (size_t)brow * N + bn + bcol;
    uint32_t asb = (uint32_t)__cvta_generic_to_shared(As) + (arow * 36 + acol) * 4;
    uint32_t bsb = (uint32_t)__cvta_generic_to_shared(Bs) + (brow * 136 + bcol) * 4;
    constexpr uint32_t ASTG = 128 * 36 * 4;
    constexpr uint32_t BSTG = 32 * 136 * 4;

    float acc[4][4][4];
    #pragma unroll
    for (int i = 0; i < 4; i++)
        #pragma unroll
        for (int j = 0; j < 4; j++)
            #pragma unroll
            for (int e = 0; e < 4; e++) acc[i][j][e] = 0.0f;

    int nK = K >> 5;
    // prefetch tile 0 into stage 0
    #pragma unroll
    for (int u = 0; u < 4; u++) cp16(asb + u * 16, Ag + u * 4);
    #pragma unroll
    for (int u = 0; u < 4; u++) cp16(bsb + u * 16, Bg + u * 4);
    CP_COMMIT();

    for (int it = 0; it < nK; it++) {
        int cur = it & 1;
        if (it + 1 < nK) {
            int nx = cur ^ 1;
            const float* ap = Ag + (it + 1) * 32;
            const float* bp = Bg + (size_t)(it + 1) * 32 * N;
            #pragma unroll
            for (int u = 0; u < 4; u++) cp16(asb + nx * ASTG + u * 16, ap + u * 4);
            #pragma unroll
            for (int u = 0; u < 4; u++) cp16(bsb + nx * BSTG + u * 16, bp + u * 4);
        }
        CP_COMMIT();
        CP_WAIT1();
        __syncthreads();

        const float* Ast = As + cur * 128 * 36;
        const float* Bst = Bs + cur * 32 * 136;
        #pragma unroll
        for (int ks = 0; ks < 4; ks++) {
            int kk = ks * 8;
            unsigned af[4][4], bf[4][2];
            #pragma unroll
            for (int mt = 0; mt < 4; mt++) {
                int m = warpM * 64 + mt * 16 + g;
                af[mt][0] = fbits(Ast[m * 36 + kk + tg]);
                af[mt][1] = fbits(Ast[(m + 8) * 36 + kk + tg]);
                af[mt][2] = fbits(Ast[m * 36 + kk + tg + 4]);
                af[mt][3] = fbits(Ast[(m + 8) * 36 + kk + tg + 4]);
            }
            #pragma unroll
            for (int nt = 0; nt < 4; nt++) {
                int n = warpN * 32 + nt * 8 + g;
                bf[nt][0] = fbits(Bst[(kk + tg) * 136 + n]);
                bf[nt][1] = fbits(Bst[(kk + tg + 4) * 136 + n]);
            }
            #pragma unroll
            for (int mt = 0; mt < 4; mt++)
                #pragma unroll
                for (int nt = 0; nt < 4; nt++)
                    mma_tf32(acc[mt][nt], af[mt], bf[nt]);
        }
        __syncthreads();
    }

    #pragma unroll
    for (int mt = 0; mt < 4; mt++) {
        int row0 = bm + warpM * 64 + mt * 16 + g;
        #pragma unroll
        for (int nt = 0; nt < 4; nt++) {
            int col = bn + warpN * 32 + nt * 8 + 2 * tg;
            float b0 = bias[col], b1 = bias[col + 1];
            float* d0 = D + (size_t)row0 * N + col;
            float* d1 = D + (size_t)(row0 + 8) * N + col;
            float v00 = acc[mt][nt][0] + b0, v01 = acc[mt][nt][1] + b1;
            float v10 = acc[mt][nt][2] + b0, v11 = acc[mt][nt][3] + b1;
            if (EPI == 1) {
                v00 = fmaxf(v00, 0.0f); v01 = fmaxf(v01, 0.0f);
                v10 = fmaxf(v10, 0.0f); v11 = fmaxf(v11, 0.0f);
            }
            if (EPI == 2) {
                float2 r0 = *(float2*)d0, r1 = *(float2*)d1;
                v00 += r0.x; v01 += r0.y; v10 += r1.x; v11 += r1.y;
            }
            *(float2*)d0 = make_float2(v00, v01);
            *(float2*)d1 = make_float2(v10, v11);
        }
    }
}

// ============================================================
// TF32 scores: S = 0.125 * Q K^T  (per b,h; K=64, 2 pipeline iters)
// Qs/Ks: [2][128][36]
// ============================================================
constexpr int SC_SMEM = (2 * 128 * 36 * 2) * 4;   // 73728 B

__global__ void __launch_bounds__(256, 2)
scores_tf32(const float* __restrict__ q, const float* __restrict__ k,
            float* __restrict__ S) {
    extern __shared__ float sm[];
    float* Qs = sm;                   // 2*128*36
    float* Ks = sm + 2 * 128 * 36;
    int tid = threadIdx.x;
    int lane = tid & 31, wid = tid >> 5;
    int warpM = wid & 1, warpN = wid >> 1;
    int g = lane >> 2, tg = lane & 3;
    int bh = blockIdx.z;
    int b = bh >> 3, nh = bh & 7;
    int t0 = blockIdx.y * 128, s0 = blockIdx.x * 128;
    const float* qb = q + ((size_t)b * T) * NC + nh * HD;
    const float* kb = k + ((size_t)b * T) * NC + nh * HD;

    int arow = tid >> 1, acol = (tid & 1) * 16;
    const float* Qg = qb + (size_t)(t0 + arow) * NC + acol;
    const float* Kg = kb + (size_t)(s0 + arow) * NC + acol;
    uint32_t qsb = (uint32_t)__cvta_generic_to_shared(Qs) + (arow * 36 + acol) * 4;
    uint32_t ksb = (uint32_t)__cvta_generic_to_shared(Ks) + (arow * 36 + acol) * 4;
    constexpr uint32_t STG = 128 * 36 * 4;

    float acc[4][4][4];
    #pragma unroll
    for (int i = 0; i < 4; i++)
        #pragma unroll
        for (int j = 0; j < 4; j++)
            #pragma unroll
            for (int e = 0; e < 4; e++) acc[i][j][e] = 0.0f;

    #pragma unroll
    for (int u = 0; u < 4; u++) cp16(qsb + u * 16, Qg + u * 4);
    #pragma unroll
    for (int u = 0; u < 4; u++) cp16(ksb + u * 16, Kg + u * 4);
    CP_COMMIT();

    #pragma unroll
    for (int it = 0; it < 2; it++) {
        int cur = it & 1;
        if (it + 1 < 2) {
            #pragma unroll
            for (int u = 0; u < 4; u++) cp16(qsb + STG + u * 16, Qg + 32 + u * 4);
            #pragma unroll
            for (int u = 0; u < 4; u++) cp16(ksb + STG + u * 16, Kg + 32 + u * 4);
        }
        CP_COMMIT();
        CP_WAIT1();
        __syncthreads();

        const float* Qst = Qs + cur * 128 * 36;
        const float* Kst = Ks + cur * 128 * 36;
        #pragma unroll
        for (int ks = 0; ks < 4; ks++) {
            int kk = ks * 8;
            unsigned af[4][4], bf[4][2];
            #pragma unroll
            for (int mt = 0; mt < 4; mt++) {
                int m = warpM * 64 + mt * 16 + g;
                af[mt][0] = fbits(Qst[m * 36 + kk + tg]);
                af[mt][1] = fbits(Qst[(m + 8) * 36 + kk + tg]);
                af[mt][2] = fbits(Qst[m * 36 + kk + tg + 4]);
                af[mt][3] = fbits(Qst[(m + 8) * 36 + kk + tg + 4]);
            }
            #pragma unroll
            for (int nt = 0; nt < 4; nt++) {
                int n = warpN * 32 + nt * 8 + g;
                bf[nt][0] = fbits(Kst[n * 36 + kk + tg]);
                bf[nt][1] = fbits(Kst[n * 36 + kk + tg + 4]);
            }
            #pragma unroll
            for (int mt = 0; mt < 4; mt++)
                #pragma unroll
                for (int nt = 0; nt < 4; nt++)
                    mma_tf32(acc[mt][nt], af[mt], bf[nt]);
        }
        __syncthreads();
    }

    float* Sb = S + (size_t)bh * T * T;
    #pragma unroll
    for (int mt = 0; mt < 4; mt++) {
        int row0 = t0 + warpM * 64 + mt * 16 + g;
        #pragma unroll
        for (int nt = 0; nt < 4; nt++) {
            int col = s0 + warpN * 32 + nt * 8 + 2 * tg;
            *(float2*)(Sb + (size_t)row0 * T + col) =
                make_float2(acc[mt][nt][0] * 0.125f, acc[mt][nt][1] * 0.125f);
            *(float2*)(Sb + (size_t)(row0 + 8) * T + col) =
                make_float2(acc[mt][nt][2] * 0.125f, acc[mt][nt][3] * 0.125f);
        }
    }
}

// ============================================================
// Row softmax over T=1280
// ============================================================
__global__ void softmax_kernel(float* __restrict__ S) {
    size_t row = blockIdx.x;
    float* p = S + row * (size_t)T;
    int tid = threadIdx.x;
    float vals[5];
    float mx = -1e30f;
    #pragma unroll
    for (int u = 0; u < 5; u++) { vals[u] = p[tid + u * 256]; mx = fmaxf(mx, vals[u]); }
    #pragma unroll
    for (int off = 16; off; off >>= 1) mx = fmaxf(mx, __shfl_xor_sync(0xFFFFFFFFu, mx, off));
    __shared__ float sm2a[8], sm2b[8];
    if ((tid & 31) == 0) sm2a[tid >> 5] = mx;
    __syncthreads();
    float bm = sm2a[0];
    #pragma unroll
    for (int w = 1; w < 8; w++) bm = fmaxf(bm, sm2a[w]);
    float ssum = 0.0f;
    #pragma unroll
    for (int u = 0; u < 5; u++) { vals[u] = __expf(vals[u] - bm); ssum += vals[u]; }
    #pragma unroll
    for (int off = 16; off; off >>= 1) ssum += __shfl_xor_sync(0xFFFFFFFFu, ssum, off);
    if ((tid & 31) == 0) sm2b[tid >> 5] = ssum;
    __syncthreads();
    float tot = sm2b[0];
    #pragma unroll
    for (int w = 1; w < 8; w++) tot += sm2b[w];
    float inv = 1.0f / tot;
    #pragma unroll
    for (int u = 0; u < 5; u++) p[tid + u * 256] = vals[u] * inv;
}

// ============================================================
// TF32 AV: Y = P @ V  (per b,h; M=1280, N=64, K=1280), pipelined
// Ps: [2][128][36], Vs: [2][32][72]
// 8 warps (4m x 2n), warp 32x32.
// ============================================================
constexpr int AV_SMEM = (2 * 128 * 36 + 2 * 32 * 72) * 4;   // 55296 B

__global__ void __launch_bounds__(256, 2)
av_tf32(const float* __restrict__ S, const float* __restrict__ v,
        float* __restrict__ y) {
    extern __shared__ float sm[];
    float* Ps = sm;                   // 2*128*36
    float* Vs = sm + 2 * 128 * 36;    // 2*32*72
    int tid = threadIdx.x;
    int lane = tid & 31, wid = tid >> 5;
    int warpM = wid & 3, warpN = wid >> 2;
    int g = lane >> 2, tg = lane & 3;
    int bh = blockIdx.y;
    int b = bh >> 3, nh = bh & 7;
    int t0 = blockIdx.x * 128;
    const float* Pb = S + (size_t)bh * T * T;
    const float* vb = v + ((size_t)b * T) * NC + nh * HD;

    int arow = tid >> 1, acol = (tid & 1) * 16;
    int vrow = tid >> 3, vcol = (tid & 7) * 8;
    const float* Pg = Pb + (size_t)(t0 + arow) * T + acol;
    const float* Vg = vb + (size_t)vrow * NC + vcol;
    uint32_t psb = (uint32_t)__cvta_generic_to_shared(Ps) + (arow * 36 + acol) * 4;
    uint32_t vsb = (uint32_t)__cvta_generic_to_shared(Vs) + (vrow * 72 + vcol) * 4;
    constexpr uint32_t PSTG = 128 * 36 * 4;
    constexpr uint32_t VSTG = 32 * 72 * 4;

    float acc[2][4][4];
    #pragma unroll
    for (int i = 0; i < 2; i++)
        #pragma unroll
        for (int j = 0; j < 4; j++)
            #pragma unroll
            for (int e = 0; e < 4; e++) acc[i][j][e] = 0.0f;

    constexpr int nK = T / 32;   // 40
    #pragma unroll
    for (int u = 0; u < 4; u++) cp16(psb + u * 16, Pg + u * 4);
    #pragma unroll
    for (int u = 0; u < 2; u++) cp16(vsb + u * 16, Vg + u * 4);
    CP_COMMIT();

    for (int it = 0; it < nK; it++) {
        int cur = it & 1;
        if (it + 1 < nK) {
            int nx = cur ^ 1;
            const float* pp = Pg + (it + 1) * 32;
            const float* vp = Vg + (size_t)(it + 1) * 32 * NC;
            #pragma unroll
            for (int u = 0; u < 4; u++) cp16(psb + nx * PSTG + u * 16, pp + u * 4);
            #pragma unroll
            for (int u = 0; u < 2; u++) cp16(vsb + nx * VSTG + u * 16, vp + u * 4);
        }
        CP_COMMIT();
        CP_WAIT1();
        __syncthreads();

        const float* Pst = Ps + cur * 128 * 36;
        const float* Vst = Vs + cur * 32 * 72;
        #pragma unroll
        for (int ks = 0; ks < 4; ks++) {
            int kk = ks * 8;
            unsigned af[2][4], bf[4][2];
            #pragma unroll
            for (int mt = 0; mt < 2; mt++) {
                int m = warpM * 32 + mt * 16 + g;
                af[mt][0] = fbits(Pst[m * 36 + kk + tg]);
                af[mt][1] = fbits(Pst[(m + 8) * 36 + kk + tg]);
                af[mt][2] = fbits(Pst[m * 36 + kk + tg + 4]);
                af[mt][3] = fbits(Pst[(m + 8) * 36 + kk + tg + 4]);
            }
            #pragma unroll
            for (int nt = 0; nt < 4; nt++) {
                int n = warpN * 32 + nt * 8 + g;
                bf[nt][0] = fbits(Vst[(kk + tg) * 72 + n]);
                bf[nt][1] = fbits(Vst[(kk + tg + 4) * 72 + n]);
            }
            #pragma unroll
            for (int mt = 0; mt < 2; mt++)
                #pragma unroll
                for (int nt = 0; nt < 4; nt++)
                    mma_tf32(acc[mt][nt], af[mt], bf[nt]);
        }
        __syncthreads();
    }

    #pragma unroll
    for (int mt = 0; mt < 2; mt++) {
        int row0 = t0 + warpM * 32 + mt * 16 + g;
        #pragma unroll
        for (int nt = 0; nt < 4; nt++) {
            int col = warpN * 32 + nt * 8 + 2 * tg;
            float* d0 = y + ((size_t)b * T + row0) * NC + nh * HD + col;
            float* d1 = y + ((size_t)b * T + row0 + 8) * NC + nh * HD + col;
            *(float2*)d0 = make_float2(acc[mt][nt][0], acc[mt][nt][1]);
            *(float2*)d1 = make_float2(acc[mt][nt][2], acc[mt][nt][3]);
        }
    }
}

// ============================================================
// host launch
// ============================================================
extern "C" void kernel_launch(void* const* d_in, const int* in_sizes, int n_in,
                              void* d_out, int out_size) {
    const float* img  = (const float*)d_in[0];
    const float* rad  = (const float*)d_in[1];
    const float* pos  = (const float*)d_in[2];
    const float* ln1w = (const float*)d_in[3];
    const float* ln1b = (const float*)d_in[4];
    const float* Wq   = (const float*)d_in[5];
    const float* bq   = (const float*)d_in[6];
    const float* Wk   = (const float*)d_in[7];
    const float* bk   = (const float*)d_in[8];
    const float* Wv   = (const float*)d_in[9];
    const float* bv   = (const float*)d_in[10];
    const float* Wo   = (const float*)d_in[11];
    const float* bo   = (const float*)d_in[12];
    const float* ln2w = (const float*)d_in[13];
    const float* ln2b = (const float*)d_in[14];
    const float* W1   = (const float*)d_in[15];
    const float* b1   = (const float*)d_in[16];
    const float* W2   = (const float*)d_in[17];
    const float* b2   = (const float*)d_in[18];
    const float* lnfw = (const float*)d_in[19];
    const float* lnfb = (const float*)d_in[20];
    float* out = (float*)d_out;

    float *x, *h, *q, *k, *v, *y, *ff, *s;
    cudaGetSymbolAddress((void**)&x,  g_x);
    cudaGetSymbolAddress((void**)&h,  g_h);
    cudaGetSymbolAddress((void**)&q,  g_q);
    cudaGetSymbolAddress((void**)&k,  g_k);
    cudaGetSymbolAddress((void**)&v,  g_v);
    cudaGetSymbolAddress((void**)&y,  g_y);
    cudaGetSymbolAddress((void**)&ff, g_ff);
    cudaGetSymbolAddress((void**)&s,  g_s);

    cudaFuncSetAttribute(gemm_tf32<0>, cudaFuncAttributeMaxDynamicSharedMemorySize, GEMM_SMEM);
    cudaFuncSetAttribute(gemm_tf32<1>, cudaFuncAttributeMaxDynamicSharedMemorySize, GEMM_SMEM);
    cudaFuncSetAttribute(gemm_tf32<2>, cudaFuncAttributeMaxDynamicSharedMemorySize, GEMM_SMEM);
    cudaFuncSetAttribute(scores_tf32,  cudaFuncAttributeMaxDynamicSharedMemorySize, SC_SMEM);
    cudaFuncSetAttribute(av_tf32,      cudaFuncAttributeMaxDynamicSharedMemorySize, AV_SMEM);

    embed_kernel<<<(MROWS * NC) / 256, 256>>>(img, rad, pos, x);

    dim3 gC(NC / 128, MROWS / 128);          // (4, 160)
    dim3 gF(FF / 128, MROWS / 128);          // (16, 160)
    dim3 gSc(T / 128, T / 128, NB * NHEADS); // (10, 10, 128)
    dim3 gAv(T / 128, NB * NHEADS);          // (10, 128)

    for (int i = 0; i < LAYERS; i++) {
        size_t wOff = (size_t)i * NC * NC;
        ln_kernel<<<MROWS, 128>>>(x, h, ln1w + i * NC, ln1b + i * NC);
        gemm_tf32<0><<<gC, 256, GEMM_SMEM>>>(h, Wq + wOff, bq + i * NC, q, MROWS, NC, NC);
        gemm_tf32<0><<<gC, 256, GEMM_SMEM>>>(h, Wk + wOff, bk + i * NC, k, MROWS, NC, NC);
        gemm_tf32<0><<<gC, 256, GEMM_SMEM>>>(h, Wv + wOff, bv + i * NC, v, MROWS, NC, NC);
        scores_tf32<<<gSc, 256, SC_SMEM>>>(q, k, s);
        softmax_kernel<<<NB * NHEADS * T, 256>>>(s);
        av_tf32<<<gAv, 256, AV_SMEM>>>(s, v, y);
        gemm_tf32<2><<<gC, 256, GEMM_SMEM>>>(y, Wo + wOff, bo + i * NC, x, MROWS, NC, NC);
        ln_kernel<<<MROWS, 128>>>(x, h, ln2w + i * NC, ln2b + i * NC);
        gemm_tf32<1><<<gF, 256, GEMM_SMEM>>>(h, W1 + (size_t)i * NC * FF, b1 + i * FF, ff,
                                             MROWS, FF, NC);
        gemm_tf32<2><<<gC, 256, GEMM_SMEM>>>(ff, W2 + (size_t)i * FF * NC, b2 + i * NC, x,
                                             MROWS, NC, FF);
    }
    lnf_out_kernel<<<MROWS, 128>>>(x, out, lnfw, lnfb);
}